// round 15
// baseline (speedup 1.0000x reference)
#include <cuda_runtime.h>
#include <cuda_fp16.h>
#include <cstdint>

// ---------------- problem constants ----------------
#define M_TOK   100352          // 32 * 64 * 49 tokens (window-gathered order)
#define CDIM    256
#define NHEADS  8
#define HD      32
#define TWIN    49
#define NWIN    2048

// scratch (all fp16 intermediates)
__device__ __half g_qkvh[3ull * M_TOK * CDIM];  // Q|K|V, window-gathered rows
__device__ __half g_xh[(size_t)M_TOK * CDIM];   // gathered x
__device__ __half g_wh[768 * CDIM];             // Wq|Wk|Wv

// ======================= helpers =======================
__device__ __forceinline__ uint32_t smem_u32(const void* p) {
    uint32_t a;
    asm("{ .reg .u64 t; cvta.to.shared.u64 t, %1; cvt.u32.u64 %0, t; }" : "=r"(a) : "l"(p));
    return a;
}
__device__ __forceinline__ void mma_f16(float c[4], const unsigned a[4], const unsigned b[2]) {
    asm volatile(
        "mma.sync.aligned.m16n8k16.row.col.f32.f16.f16.f32 "
        "{%0,%1,%2,%3}, {%4,%5,%6,%7}, {%8,%9}, {%0,%1,%2,%3};"
        : "+f"(c[0]), "+f"(c[1]), "+f"(c[2]), "+f"(c[3])
        : "r"(a[0]), "r"(a[1]), "r"(a[2]), "r"(a[3]), "r"(b[0]), "r"(b[1]));
}
__device__ __forceinline__ unsigned pack_h2(float lo, float hi) {
    __half2 h = __float22half2_rn(make_float2(lo, hi));
    return *(unsigned*)&h;
}

#define CP_ASYNC16(dst, src) \
    asm volatile("cp.async.cg.shared.global [%0], [%1], 16;" :: "r"(dst), "l"(src))
#define CP_COMMIT() asm volatile("cp.async.commit_group;" ::: "memory")
#define CP_WAIT1()  asm volatile("cp.async.wait_group 1;" ::: "memory")
#define CP_WAIT0()  asm volatile("cp.async.wait_group 0;" ::: "memory")

// ================= Kernel 0: gather + fp16 pre-convert (coalesced) =================
__global__ void __launch_bounds__(256) pre_cvt_h(
    const float* __restrict__ x,
    const float* __restrict__ Wq, const float* __restrict__ Wk, const float* __restrict__ Wv)
{
    const int blk  = blockIdx.x;
    const int rloc = threadIdx.x >> 5;
    const int lane = threadIdx.x & 31;

    const float* src;
    __half* dst;
    if (blk < 12544) {
        int p  = blk * 8 + rloc;
        int b  = p / 3136;
        int r  = p - b * 3136;
        int w  = r / 49;
        int t  = r - w * 49;
        int wy = w >> 3, wx = w & 7;
        int ty = t / 7,  tx = t - ty * 7;
        src = x + (size_t)((b * 56 + wy * 7 + ty) * 56 + wx * 7 + tx) * CDIM + lane * 8;
        dst = g_xh + (size_t)p * CDIM + lane * 8;
    } else {
        int r  = (blk - 12544) * 8 + rloc;
        int pr = r >> 8, wr = r & 255;
        const float* W = (pr == 0) ? Wq : ((pr == 1) ? Wk : Wv);
        src = W + (size_t)wr * CDIM + lane * 8;
        dst = g_wh + (size_t)r * CDIM + lane * 8;
    }
    float4 v0 = *(const float4*)(src);
    float4 v1 = *(const float4*)(src + 4);
    __half2 o[4];
    o[0] = __float22half2_rn(make_float2(v0.x, v0.y));
    o[1] = __float22half2_rn(make_float2(v0.z, v0.w));
    o[2] = __float22half2_rn(make_float2(v1.x, v1.y));
    o[3] = __float22half2_rn(make_float2(v1.z, v1.w));
    *(uint4*)dst = *(uint4*)o;
}

// ================= Kernel 1: QKV projection (fp16 HMMA, 256 thr / 32x64 warp tiles) =================
#define HST 40
#define STAGE_HALVES (2 * 128 * HST)
#define PROJ_SMEM_BYTES (3 * STAGE_HALVES * 2)   // 61440

__global__ void __launch_bounds__(256, 2) qkv_proj_fp16(
    const float* __restrict__ bq, const float* __restrict__ bk, const float* __restrict__ bv)
{
    extern __shared__ __align__(16) __half hsm[];

    const int tid  = threadIdx.x;
    const int warp = tid >> 5;
    const int lane = tid & 31;
    const int g    = lane >> 2;
    const int tig  = lane & 3;
    const int wm   = warp & 3;      // 0..3: 32-row m-tile
    const int wn   = warp >> 2;     // 0..1: 64-col n-tile

    const int p_block = blockIdx.y * 128;
    const int nb      = blockIdx.x;
    const int proj    = nb >> 1;
    const int dloc    = (nb & 1) * 128;
    const float* __restrict__ bias = (proj == 0) ? bq : ((proj == 1) ? bk : bv);

    // loader: idx covers 128 rows x 4 segs (8 halves each) per matrix, 2 iters
    const uint32_t sbase = smem_u32(hsm);

    auto issue_stage = [&](int stage, int chunk) {
        const uint32_t sA = sbase + (uint32_t)(stage * STAGE_HALVES) * 2;
        const uint32_t sB = sA + 128 * HST * 2;
        const int ko = chunk * 32;
        #pragma unroll
        for (int i = 0; i < 2; i++) {
            int idx = tid + i * 256;          // 0..511
            int row = idx >> 2;               // 0..127
            int seg = idx & 3;
            const uint32_t ro = (uint32_t)(row * HST + seg * 8) * 2;
            CP_ASYNC16(sA + ro, g_xh + (size_t)(p_block + row) * CDIM + ko + seg * 8);
            CP_ASYNC16(sB + ro, g_wh + (size_t)(nb * 128 + row) * CDIM + ko + seg * 8);
        }
        CP_COMMIT();
    };

    issue_stage(0, 0);
    issue_stage(1, 1);

    float acc[2][8][4] = {};

    int stage = 0;
    for (int kt = 0; kt < 8; kt++) {
        if (kt < 7) { CP_WAIT1(); } else { CP_WAIT0(); }
        __syncthreads();

        if (kt + 2 < 8) {
            int ns = stage + 2; if (ns >= 3) ns -= 3;
            issue_stage(ns, kt + 2);
        }

        const uint32_t* As32 = (const uint32_t*)(hsm + stage * STAGE_HALVES);
        const uint32_t* Bs32 = As32 + 128 * (HST / 2);

        #pragma unroll
        for (int ks = 0; ks < 2; ks++) {
            const int ko = ks * 8;
            unsigned a[2][4];
            unsigned b[8][2];
            #pragma unroll
            for (int mt = 0; mt < 2; mt++) {
                int row = wm * 32 + mt * 16 + g;
                a[mt][0] = As32[row * 20 + ko + tig];
                a[mt][1] = As32[(row + 8) * 20 + ko + tig];
                a[mt][2] = As32[row * 20 + ko + 4 + tig];
                a[mt][3] = As32[(row + 8) * 20 + ko + 4 + tig];
            }
            #pragma unroll
            for (int nt = 0; nt < 8; nt++) {
                int nrow = wn * 64 + nt * 8 + g;
                b[nt][0] = Bs32[nrow * 20 + ko + tig];
                b[nt][1] = Bs32[nrow * 20 + ko + 4 + tig];
            }
            #pragma unroll
            for (int mt = 0; mt < 2; mt++)
                #pragma unroll
                for (int nt = 0; nt < 8; nt++)
                    mma_f16(acc[mt][nt], a[mt], b[nt]);
        }

        stage++; if (stage == 3) stage = 0;
    }

    // ---- epilogue: bias add + fp16 store ----
    const size_t proj_off = (size_t)proj * M_TOK * CDIM;
    float bvs[8][2];
    #pragma unroll
    for (int nt = 0; nt < 8; nt++) {
        int d = dloc + wn * 64 + nt * 8 + tig * 2;
        bvs[nt][0] = bias[d];
        bvs[nt][1] = bias[d + 1];
    }
    #pragma unroll
    for (int mt = 0; mt < 2; mt++) {
        int p0 = p_block + wm * 32 + mt * 16 + g;
        __half* r0 = g_qkvh + proj_off + (size_t)p0 * CDIM;
        __half* r1 = r0 + 8 * CDIM;
        #pragma unroll
        for (int nt = 0; nt < 8; nt++) {
            int d = dloc + wn * 64 + nt * 8 + tig * 2;
            *(unsigned*)(r0 + d) = pack_h2(acc[mt][nt][0] + bvs[nt][0], acc[mt][nt][1] + bvs[nt][1]);
            *(unsigned*)(r1 + d) = pack_h2(acc[mt][nt][2] + bvs[nt][0], acc[mt][nt][3] + bvs[nt][1]);
        }
    }
}

// ================= Kernel 2: fp16 tensor-core attention (round-14, unchanged) =================
#define QH_ST 40
#define VT_ST 72

__global__ void __launch_bounds__(128, 8) attn_kernel(float* __restrict__ out)
{
    __shared__ __align__(16) __half qs[64 * QH_ST];
    __shared__ __align__(16) __half ks[56 * QH_ST];
    __shared__ __align__(16) __half vt[32 * VT_ST];

    const int w   = blockIdx.x;
    const int h   = blockIdx.y;
    const int tid = threadIdx.x;

    const size_t base = (size_t)w * TWIN * CDIM + (size_t)h * HD;
    const uint32_t qs_b = smem_u32(qs);
    const uint32_t ks_b = smem_u32(ks);

    // ---- cp.async q,k issued FIRST ----
    for (int idx = tid; idx < 2 * TWIN * 4; idx += 128) {
        int mat = (idx >= TWIN * 4) ? 1 : 0;
        int rem = idx - mat * (TWIN * 4);
        int t   = rem >> 2;
        int seg = rem & 3;
        uint32_t dst = (mat ? ks_b : qs_b) + (uint32_t)(t * QH_ST + seg * 8) * 2;
        CP_ASYNC16(dst, g_qkvh + (size_t)mat * M_TOK * CDIM + base + (size_t)t * CDIM + seg * 8);
    }
    CP_COMMIT();

    // ---- zero pads (overlap with cp.async) ----
    for (int i = tid; i < 15 * QH_ST; i += 128) qs[49 * QH_ST + i] = __half(0.f);
    for (int i = tid; i < 7 * QH_ST; i += 128)  ks[49 * QH_ST + i] = __half(0.f);
    for (int i = tid; i < 32 * 16; i += 128) {
        int d = i >> 4, c = 49 + (i & 15);
        vt[d * VT_ST + c] = __half(0.f);
    }

    // ---- v transposed (LDG+STS, overlaps cp.async in flight) ----
    for (int idx = tid; idx < TWIN * 4; idx += 128) {
        int t   = idx >> 2;
        int seg = idx & 3;
        uint4 raw = *(const uint4*)(g_qkvh + (size_t)2 * M_TOK * CDIM + base + (size_t)t * CDIM + seg * 8);
        __half hv[8];
        *(uint4*)hv = raw;
        #pragma unroll
        for (int i = 0; i < 8; i++)
            vt[(seg * 8 + i) * VT_ST + t] = hv[i];
    }
    CP_WAIT0();
    __syncthreads();

    const int warp = tid >> 5;
    const int lane = tid & 31;
    const int g    = lane >> 2;
    const int tig  = lane & 3;
    const int i0   = warp * 16;

    const uint32_t* qw = (const uint32_t*)qs;
    const uint32_t* kw = (const uint32_t*)ks;
    const uint32_t* vw = (const uint32_t*)vt;

    float acc[7][4] = {};
    #pragma unroll
    for (int ks16 = 0; ks16 < 2; ks16++) {
        const int c0 = ks16 * 8;
        unsigned a[4];
        a[0] = qw[(i0 + g) * 20 + c0 + tig];
        a[1] = qw[(i0 + g + 8) * 20 + c0 + tig];
        a[2] = qw[(i0 + g) * 20 + c0 + 4 + tig];
        a[3] = qw[(i0 + g + 8) * 20 + c0 + 4 + tig];
        #pragma unroll
        for (int nt = 0; nt < 7; nt++) {
            unsigned b[2];
            b[0] = kw[(nt * 8 + g) * 20 + c0 + tig];
            b[1] = kw[(nt * 8 + g) * 20 + c0 + 4 + tig];
            mma_f16(acc[nt], a, b);
        }
    }

    #pragma unroll
    for (int nt = 0; nt < 7; nt++) {
        acc[nt][0] *= 0.0625f; acc[nt][1] *= 0.0625f;
        acc[nt][2] *= 0.0625f; acc[nt][3] *= 0.0625f;
    }
    acc[6][1] = -1e30f; acc[6][3] = -1e30f;
    if (tig > 0) { acc[6][0] = -1e30f; acc[6][2] = -1e30f; }

    float m0 = -1e30f, m1 = -1e30f;
    #pragma unroll
    for (int nt = 0; nt < 7; nt++) {
        m0 = fmaxf(m0, fmaxf(acc[nt][0], acc[nt][1]));
        m1 = fmaxf(m1, fmaxf(acc[nt][2], acc[nt][3]));
    }
    m0 = fmaxf(m0, __shfl_xor_sync(0xffffffffu, m0, 1));
    m0 = fmaxf(m0, __shfl_xor_sync(0xffffffffu, m0, 2));
    m1 = fmaxf(m1, __shfl_xor_sync(0xffffffffu, m1, 1));
    m1 = fmaxf(m1, __shfl_xor_sync(0xffffffffu, m1, 2));

    float s0 = 0.f, s1 = 0.f;
    #pragma unroll
    for (int nt = 0; nt < 7; nt++) {
        acc[nt][0] = __expf(acc[nt][0] - m0);
        acc[nt][1] = __expf(acc[nt][1] - m0);
        acc[nt][2] = __expf(acc[nt][2] - m1);
        acc[nt][3] = __expf(acc[nt][3] - m1);
        s0 += acc[nt][0] + acc[nt][1];
        s1 += acc[nt][2] + acc[nt][3];
    }
    s0 += __shfl_xor_sync(0xffffffffu, s0, 1);
    s0 += __shfl_xor_sync(0xffffffffu, s0, 2);
    s1 += __shfl_xor_sync(0xffffffffu, s1, 1);
    s1 += __shfl_xor_sync(0xffffffffu, s1, 2);
    const float inv0 = 1.f / s0, inv1 = 1.f / s1;
    #pragma unroll
    for (int nt = 0; nt < 7; nt++) {
        acc[nt][0] *= inv0; acc[nt][1] *= inv0;
        acc[nt][2] *= inv1; acc[nt][3] *= inv1;
    }

    float oacc[4][4] = {};
    #pragma unroll
    for (int t = 0; t < 4; t++) {
        const int n0 = 2 * t, n1 = 2 * t + 1;
        unsigned pa[4];
        pa[0] = pack_h2(acc[n0][0], acc[n0][1]);
        pa[1] = pack_h2(acc[n0][2], acc[n0][3]);
        pa[2] = (n1 < 7) ? pack_h2(acc[n1][0], acc[n1][1]) : 0u;
        pa[3] = (n1 < 7) ? pack_h2(acc[n1][2], acc[n1][3]) : 0u;
        #pragma unroll
        for (int dt = 0; dt < 4; dt++) {
            unsigned b[2];
            b[0] = vw[(dt * 8 + g) * 36 + 8 * t + tig];
            b[1] = vw[(dt * 8 + g) * 36 + 8 * t + tig + 4];
            mma_f16(oacc[dt], pa, b);
        }
    }

    const int row0 = i0 + g;
    const int row1 = i0 + 8 + g;
    if (row0 < TWIN) {
        float* o = out + ((size_t)w * TWIN + row0) * CDIM + (size_t)h * HD;
        #pragma unroll
        for (int dt = 0; dt < 4; dt++)
            *(float2*)&o[dt * 8 + tig * 2] = make_float2(oacc[dt][0], oacc[dt][1]);
    }
    if (row1 < TWIN) {
        float* o = out + ((size_t)w * TWIN + row1) * CDIM + (size_t)h * HD;
        #pragma unroll
        for (int dt = 0; dt < 4; dt++)
            *(float2*)&o[dt * 8 + tig * 2] = make_float2(oacc[dt][2], oacc[dt][3]);
    }
}

// ================= launch =================
extern "C" void kernel_launch(void* const* d_in, const int* in_sizes, int n_in,
                              void* d_out, int out_size) {
    const float* x  = (const float*)d_in[0];
    const float* Wq = (const float*)d_in[1];
    const float* bq = (const float*)d_in[2];
    const float* Wk = (const float*)d_in[3];
    const float* bk = (const float*)d_in[4];
    const float* Wv = (const float*)d_in[5];
    const float* bv = (const float*)d_in[6];
    float* out = (float*)d_out;

    cudaFuncSetAttribute(qkv_proj_fp16,
                         cudaFuncAttributeMaxDynamicSharedMemorySize, PROJ_SMEM_BYTES);

    pre_cvt_h<<<12640, 256>>>(x, Wq, Wk, Wv);

    dim3 g1(6, M_TOK / 128);
    qkv_proj_fp16<<<g1, 256, PROJ_SMEM_BYTES>>>(bq, bk, bv);

    dim3 g2(NWIN, NHEADS);
    attn_kernel<<<g2, 128>>>(out);
}

// round 16
// speedup vs baseline: 1.0062x; 1.0062x over previous
#include <cuda_runtime.h>
#include <cuda_fp16.h>
#include <cstdint>

// ---------------- problem constants ----------------
#define M_TOK   100352          // 32 * 64 * 49 tokens (window-gathered order)
#define CDIM    256
#define NHEADS  8
#define HD      32
#define TWIN    49
#define NWIN    2048

// scratch (all fp16 intermediates)
__device__ __half g_qkvh[3ull * M_TOK * CDIM];  // Q|K|V, window-gathered rows
__device__ __half g_xh[(size_t)M_TOK * CDIM];   // gathered x
__device__ __half g_wh[768 * CDIM];             // Wq|Wk|Wv

// ======================= helpers =======================
__device__ __forceinline__ uint32_t smem_u32(const void* p) {
    uint32_t a;
    asm("{ .reg .u64 t; cvta.to.shared.u64 t, %1; cvt.u32.u64 %0, t; }" : "=r"(a) : "l"(p));
    return a;
}
__device__ __forceinline__ void mma_f16(float c[4], const unsigned a[4], const unsigned b[2]) {
    asm volatile(
        "mma.sync.aligned.m16n8k16.row.col.f32.f16.f16.f32 "
        "{%0,%1,%2,%3}, {%4,%5,%6,%7}, {%8,%9}, {%0,%1,%2,%3};"
        : "+f"(c[0]), "+f"(c[1]), "+f"(c[2]), "+f"(c[3])
        : "r"(a[0]), "r"(a[1]), "r"(a[2]), "r"(a[3]), "r"(b[0]), "r"(b[1]));
}
__device__ __forceinline__ unsigned pack_h2(float lo, float hi) {
    __half2 h = __float22half2_rn(make_float2(lo, hi));
    return *(unsigned*)&h;
}

#define CP_ASYNC16(dst, src) \
    asm volatile("cp.async.cg.shared.global [%0], [%1], 16;" :: "r"(dst), "l"(src))
#define CP_COMMIT() asm volatile("cp.async.commit_group;" ::: "memory")
#define CP_WAIT1()  asm volatile("cp.async.wait_group 1;" ::: "memory")
#define CP_WAIT0()  asm volatile("cp.async.wait_group 0;" ::: "memory")

// ================= Kernel 0: gather + fp16 pre-convert (coalesced) =================
__global__ void __launch_bounds__(256) pre_cvt_h(
    const float* __restrict__ x,
    const float* __restrict__ Wq, const float* __restrict__ Wk, const float* __restrict__ Wv)
{
    const int blk  = blockIdx.x;
    const int rloc = threadIdx.x >> 5;
    const int lane = threadIdx.x & 31;

    const float* src;
    __half* dst;
    if (blk < 12544) {
        int p  = blk * 8 + rloc;
        int b  = p / 3136;
        int r  = p - b * 3136;
        int w  = r / 49;
        int t  = r - w * 49;
        int wy = w >> 3, wx = w & 7;
        int ty = t / 7,  tx = t - ty * 7;
        src = x + (size_t)((b * 56 + wy * 7 + ty) * 56 + wx * 7 + tx) * CDIM + lane * 8;
        dst = g_xh + (size_t)p * CDIM + lane * 8;
    } else {
        int r  = (blk - 12544) * 8 + rloc;
        int pr = r >> 8, wr = r & 255;
        const float* W = (pr == 0) ? Wq : ((pr == 1) ? Wk : Wv);
        src = W + (size_t)wr * CDIM + lane * 8;
        dst = g_wh + (size_t)r * CDIM + lane * 8;
    }
    float4 v0 = *(const float4*)(src);
    float4 v1 = *(const float4*)(src + 4);
    __half2 o[4];
    o[0] = __float22half2_rn(make_float2(v0.x, v0.y));
    o[1] = __float22half2_rn(make_float2(v0.z, v0.w));
    o[2] = __float22half2_rn(make_float2(v1.x, v1.y));
    o[3] = __float22half2_rn(make_float2(v1.z, v1.w));
    *(uint4*)dst = *(uint4*)o;
}

// ================= Kernel 1: QKV projection (fp16 HMMA, round-14 version) =================
#define HST 40
#define STAGE_HALVES (2 * 128 * HST)
#define PROJ_SMEM_BYTES (3 * STAGE_HALVES * 2)   // 61440

__global__ void __launch_bounds__(128) qkv_proj_fp16(
    const float* __restrict__ bq, const float* __restrict__ bk, const float* __restrict__ bv)
{
    extern __shared__ __align__(16) __half hsm[];

    const int tid  = threadIdx.x;
    const int warp = tid >> 5;
    const int lane = tid & 31;
    const int g    = lane >> 2;
    const int tig  = lane & 3;
    const int wm   = warp >> 1;
    const int wn   = warp & 1;

    const int p_block = blockIdx.y * 128;
    const int nb      = blockIdx.x;
    const int proj    = nb >> 1;
    const int dloc    = (nb & 1) * 128;
    const float* __restrict__ bias = (proj == 0) ? bq : ((proj == 1) ? bk : bv);

    const int lrow = tid >> 2;
    const int seg  = tid & 3;
    const __half* Ag = g_xh + (size_t)(p_block + lrow) * CDIM + seg * 8;
    const __half* Bg = g_wh + (size_t)(nb * 128 + lrow) * CDIM + seg * 8;
    const uint32_t sbase = smem_u32(hsm);

    auto issue_stage = [&](int stage, int chunk) {
        const uint32_t sA = sbase + (uint32_t)(stage * STAGE_HALVES) * 2;
        const uint32_t sB = sA + 128 * HST * 2;
        const int ko = chunk * 32;
        #pragma unroll
        for (int i = 0; i < 4; i++) {
            const uint32_t ro = (uint32_t)((lrow + 32 * i) * HST + seg * 8) * 2;
            CP_ASYNC16(sA + ro, Ag + (size_t)(32 * i) * CDIM + ko);
            CP_ASYNC16(sB + ro, Bg + (size_t)(32 * i) * CDIM + ko);
        }
        CP_COMMIT();
    };

    issue_stage(0, 0);
    issue_stage(1, 1);

    float acc[4][8][4] = {};

    int stage = 0;
    for (int kt = 0; kt < 8; kt++) {
        if (kt < 7) { CP_WAIT1(); } else { CP_WAIT0(); }
        __syncthreads();

        if (kt + 2 < 8) {
            int ns = stage + 2; if (ns >= 3) ns -= 3;
            issue_stage(ns, kt + 2);
        }

        const uint32_t* As32 = (const uint32_t*)(hsm + stage * STAGE_HALVES);
        const uint32_t* Bs32 = As32 + 128 * (HST / 2);

        #pragma unroll
        for (int ks = 0; ks < 2; ks++) {
            const int ko = ks * 8;
            unsigned a[4][4];
            unsigned b[8][2];
            #pragma unroll
            for (int mt = 0; mt < 4; mt++) {
                int row = wm * 64 + mt * 16 + g;
                a[mt][0] = As32[row * 20 + ko + tig];
                a[mt][1] = As32[(row + 8) * 20 + ko + tig];
                a[mt][2] = As32[row * 20 + ko + 4 + tig];
                a[mt][3] = As32[(row + 8) * 20 + ko + 4 + tig];
            }
            #pragma unroll
            for (int nt = 0; nt < 8; nt++) {
                int nrow = wn * 64 + nt * 8 + g;
                b[nt][0] = Bs32[nrow * 20 + ko + tig];
                b[nt][1] = Bs32[nrow * 20 + ko + 4 + tig];
            }
            #pragma unroll
            for (int mt = 0; mt < 4; mt++)
                #pragma unroll
                for (int nt = 0; nt < 8; nt++)
                    mma_f16(acc[mt][nt], a[mt], b[nt]);
        }

        stage++; if (stage == 3) stage = 0;
    }

    // ---- epilogue: bias add + fp16 store ----
    const size_t proj_off = (size_t)proj * M_TOK * CDIM;
    float bvs[8][2];
    #pragma unroll
    for (int nt = 0; nt < 8; nt++) {
        int d = dloc + wn * 64 + nt * 8 + tig * 2;
        bvs[nt][0] = bias[d];
        bvs[nt][1] = bias[d + 1];
    }
    #pragma unroll
    for (int mt = 0; mt < 4; mt++) {
        int p0 = p_block + wm * 64 + mt * 16 + g;
        __half* r0 = g_qkvh + proj_off + (size_t)p0 * CDIM;
        __half* r1 = r0 + 8 * CDIM;
        #pragma unroll
        for (int nt = 0; nt < 8; nt++) {
            int d = dloc + wn * 64 + nt * 8 + tig * 2;
            *(unsigned*)(r0 + d) = pack_h2(acc[mt][nt][0] + bvs[nt][0], acc[mt][nt][1] + bvs[nt][1]);
            *(unsigned*)(r1 + d) = pack_h2(acc[mt][nt][2] + bvs[nt][0], acc[mt][nt][3] + bvs[nt][1]);
        }
    }
}

// ================= Kernel 2: fp16 attention, ONE WINDOW per CTA (warp = head) =================
// smem (halves): QS [64][264] @0 (rows 49..63 zero), KS [56][264] @16896 (rows 49..55 zero),
//                VT [256][72] @31680 (V transposed; token cols 49..63 zero)
#define AQ_ST 264
#define AVT_ST 72
#define SM_QS 0
#define SM_KS 16896
#define SM_VT 31680
#define ATTN_SMEM_BYTES (50112 * 2)   // 100224

__global__ void __launch_bounds__(256, 2) attn_kernel(float* __restrict__ out)
{
    extern __shared__ __align__(16) __half asmem[];
    __half* QS = asmem + SM_QS;
    __half* KS = asmem + SM_KS;
    __half* VT = asmem + SM_VT;

    const int w   = blockIdx.x;   // window 0..2047
    const int tid = threadIdx.x;  // 256

    const size_t base = (size_t)w * TWIN * CDIM;
    const uint32_t qs_b = smem_u32(QS);
    const uint32_t ks_b = smem_u32(KS);

    // ---- cp.async Q,K: full rows (49 x 256 halves each), issued first ----
    for (int idx = tid; idx < 2 * TWIN * 32; idx += 256) {
        int mat = (idx >= TWIN * 32) ? 1 : 0;
        int rem = idx - mat * (TWIN * 32);
        int t   = rem >> 5;
        int seg = rem & 31;
        uint32_t dst = (mat ? ks_b : qs_b) + (uint32_t)(t * AQ_ST + seg * 8) * 2;
        CP_ASYNC16(dst, g_qkvh + (size_t)mat * M_TOK * CDIM + base + (size_t)t * CDIM + seg * 8);
    }
    CP_COMMIT();

    // ---- zero pads (overlap with cp.async) ----
    for (int i = tid; i < 15 * AQ_ST / 8; i += 256)
        *(uint4*)(QS + 49 * AQ_ST + i * 8) = make_uint4(0, 0, 0, 0);
    for (int i = tid; i < 7 * AQ_ST / 8; i += 256)
        *(uint4*)(KS + 49 * AQ_ST + i * 8) = make_uint4(0, 0, 0, 0);
    {   // vt token cols 49..63, one d-row per thread (tid == d)
        __half* vr = VT + tid * AVT_ST;
        #pragma unroll
        for (int c = 49; c < 64; c++) vr[c] = __half(0.f);
    }

    // ---- V transposed: vt[d][t] = V[t][d]; token-fastest mapping (bank-safe) ----
    for (int idx = tid; idx < TWIN * 32; idx += 256) {
        int t   = idx % TWIN;
        int seg = idx / TWIN;        // 0..31
        uint4 raw = *(const uint4*)(g_qkvh + (size_t)2 * M_TOK * CDIM + base + (size_t)t * CDIM + seg * 8);
        __half hv[8];
        *(uint4*)hv = raw;
        #pragma unroll
        for (int i = 0; i < 8; i++)
            VT[(seg * 8 + i) * AVT_ST + t] = hv[i];
    }
    CP_WAIT0();
    __syncthreads();

    const int warp = tid >> 5;    // = head h
    const int lane = tid & 31;
    const int g    = lane >> 2;
    const int tig  = lane & 3;
    const int h    = warp;
    const int hw   = h * 16;      // head word offset within 132-word rows

    const uint32_t* qw = (const uint32_t*)QS;   // word stride 132
    const uint32_t* kw = (const uint32_t*)KS;
    const uint32_t* vw = (const uint32_t*)VT;   // word stride 36

    for (int qt = 0; qt < 4; qt++) {
        const int i0 = qt * 16;

        // ---- QK^T ----
        float acc[7][4] = {};
        #pragma unroll
        for (int ks16 = 0; ks16 < 2; ks16++) {
            const int c0 = hw + ks16 * 8;
            unsigned a[4];
            a[0] = qw[(i0 + g) * 132 + c0 + tig];
            a[1] = qw[(i0 + g + 8) * 132 + c0 + tig];
            a[2] = qw[(i0 + g) * 132 + c0 + 4 + tig];
            a[3] = qw[(i0 + g + 8) * 132 + c0 + 4 + tig];
            #pragma unroll
            for (int nt = 0; nt < 7; nt++) {
                unsigned b[2];
                b[0] = kw[(nt * 8 + g) * 132 + c0 + tig];
                b[1] = kw[(nt * 8 + g) * 132 + c0 + 4 + tig];
                mma_f16(acc[nt], a, b);
            }
        }

        // ---- scale + mask padded key cols (j >= 49; tile 6 covers 48..55) ----
        #pragma unroll
        for (int nt = 0; nt < 7; nt++) {
            acc[nt][0] *= 0.0625f; acc[nt][1] *= 0.0625f;
            acc[nt][2] *= 0.0625f; acc[nt][3] *= 0.0625f;
        }
        acc[6][1] = -1e30f; acc[6][3] = -1e30f;
        if (tig > 0) { acc[6][0] = -1e30f; acc[6][2] = -1e30f; }

        // ---- softmax on fragments ----
        float m0 = -1e30f, m1 = -1e30f;
        #pragma unroll
        for (int nt = 0; nt < 7; nt++) {
            m0 = fmaxf(m0, fmaxf(acc[nt][0], acc[nt][1]));
            m1 = fmaxf(m1, fmaxf(acc[nt][2], acc[nt][3]));
        }
        m0 = fmaxf(m0, __shfl_xor_sync(0xffffffffu, m0, 1));
        m0 = fmaxf(m0, __shfl_xor_sync(0xffffffffu, m0, 2));
        m1 = fmaxf(m1, __shfl_xor_sync(0xffffffffu, m1, 1));
        m1 = fmaxf(m1, __shfl_xor_sync(0xffffffffu, m1, 2));

        float s0 = 0.f, s1 = 0.f;
        #pragma unroll
        for (int nt = 0; nt < 7; nt++) {
            acc[nt][0] = __expf(acc[nt][0] - m0);
            acc[nt][1] = __expf(acc[nt][1] - m0);
            acc[nt][2] = __expf(acc[nt][2] - m1);
            acc[nt][3] = __expf(acc[nt][3] - m1);
            s0 += acc[nt][0] + acc[nt][1];
            s1 += acc[nt][2] + acc[nt][3];
        }
        s0 += __shfl_xor_sync(0xffffffffu, s0, 1);
        s0 += __shfl_xor_sync(0xffffffffu, s0, 2);
        s1 += __shfl_xor_sync(0xffffffffu, s1, 1);
        s1 += __shfl_xor_sync(0xffffffffu, s1, 2);
        const float inv0 = 1.f / s0, inv1 = 1.f / s1;
        #pragma unroll
        for (int nt = 0; nt < 7; nt++) {
            acc[nt][0] *= inv0; acc[nt][1] *= inv0;
            acc[nt][2] *= inv1; acc[nt][3] *= inv1;
        }

        // ---- PV: C-frag == A-frag (pack to half2) ----
        float oacc[4][4] = {};
        #pragma unroll
        for (int t = 0; t < 4; t++) {
            const int n0 = 2 * t, n1 = 2 * t + 1;
            unsigned pa[4];
            pa[0] = pack_h2(acc[n0][0], acc[n0][1]);
            pa[1] = pack_h2(acc[n0][2], acc[n0][3]);
            pa[2] = (n1 < 7) ? pack_h2(acc[n1][0], acc[n1][1]) : 0u;
            pa[3] = (n1 < 7) ? pack_h2(acc[n1][2], acc[n1][3]) : 0u;
            #pragma unroll
            for (int dt = 0; dt < 4; dt++) {
                unsigned b[2];
                b[0] = vw[(h * 32 + dt * 8 + g) * 36 + 8 * t + tig];
                b[1] = vw[(h * 32 + dt * 8 + g) * 36 + 8 * t + tig + 4];
                mma_f16(oacc[dt], pa, b);
            }
        }

        // ---- store ----
        const int row0 = i0 + g;
        const int row1 = i0 + 8 + g;
        if (row0 < TWIN) {
            float* o = out + ((size_t)w * TWIN + row0) * CDIM + (size_t)h * HD;
            #pragma unroll
            for (int dt = 0; dt < 4; dt++)
                *(float2*)&o[dt * 8 + tig * 2] = make_float2(oacc[dt][0], oacc[dt][1]);
        }
        if (row1 < TWIN) {
            float* o = out + ((size_t)w * TWIN + row1) * CDIM + (size_t)h * HD;
            #pragma unroll
            for (int dt = 0; dt < 4; dt++)
                *(float2*)&o[dt * 8 + tig * 2] = make_float2(oacc[dt][2], oacc[dt][3]);
        }
    }
}

// ================= launch =================
extern "C" void kernel_launch(void* const* d_in, const int* in_sizes, int n_in,
                              void* d_out, int out_size) {
    const float* x  = (const float*)d_in[0];
    const float* Wq = (const float*)d_in[1];
    const float* bq = (const float*)d_in[2];
    const float* Wk = (const float*)d_in[3];
    const float* bk = (const float*)d_in[4];
    const float* Wv = (const float*)d_in[5];
    const float* bv = (const float*)d_in[6];
    float* out = (float*)d_out;

    cudaFuncSetAttribute(qkv_proj_fp16,
                         cudaFuncAttributeMaxDynamicSharedMemorySize, PROJ_SMEM_BYTES);
    cudaFuncSetAttribute(attn_kernel,
                         cudaFuncAttributeMaxDynamicSharedMemorySize, ATTN_SMEM_BYTES);

    pre_cvt_h<<<12640, 256>>>(x, Wq, Wk, Wv);

    dim3 g1(6, M_TOK / 128);
    qkv_proj_fp16<<<g1, 128, PROJ_SMEM_BYTES>>>(bq, bk, bv);

    attn_kernel<<<NWIN, 256, ATTN_SMEM_BYTES>>>(out);
}

// round 17
// speedup vs baseline: 1.0150x; 1.0087x over previous
#include <cuda_runtime.h>
#include <cuda_fp16.h>
#include <cstdint>

// ---------------- problem constants ----------------
#define M_TOK   100352          // 32 * 64 * 49 tokens (window-gathered order)
#define CDIM    256
#define NHEADS  8
#define HD      32
#define TWIN    49
#define NWIN    2048

// scratch (all fp16 intermediates)
__device__ __half g_qkvh[3ull * M_TOK * CDIM];  // Q|K|V, window-gathered rows
__device__ __half g_xh[(size_t)M_TOK * CDIM];   // gathered x
__device__ __half g_wh[768 * CDIM];             // Wq|Wk|Wv

// ======================= helpers =======================
__device__ __forceinline__ uint32_t smem_u32(const void* p) {
    uint32_t a;
    asm("{ .reg .u64 t; cvta.to.shared.u64 t, %1; cvt.u32.u64 %0, t; }" : "=r"(a) : "l"(p));
    return a;
}
__device__ __forceinline__ void mma_f16(float c[4], const unsigned a[4], const unsigned b[2]) {
    asm volatile(
        "mma.sync.aligned.m16n8k16.row.col.f32.f16.f16.f32 "
        "{%0,%1,%2,%3}, {%4,%5,%6,%7}, {%8,%9}, {%0,%1,%2,%3};"
        : "+f"(c[0]), "+f"(c[1]), "+f"(c[2]), "+f"(c[3])
        : "r"(a[0]), "r"(a[1]), "r"(a[2]), "r"(a[3]), "r"(b[0]), "r"(b[1]));
}
__device__ __forceinline__ unsigned pack_h2(float lo, float hi) {
    __half2 h = __float22half2_rn(make_float2(lo, hi));
    return *(unsigned*)&h;
}

#define CP_ASYNC16(dst, src) \
    asm volatile("cp.async.cg.shared.global [%0], [%1], 16;" :: "r"(dst), "l"(src))
#define CP_COMMIT() asm volatile("cp.async.commit_group;" ::: "memory")
#define CP_WAIT2()  asm volatile("cp.async.wait_group 2;" ::: "memory")
#define CP_WAIT1()  asm volatile("cp.async.wait_group 1;" ::: "memory")
#define CP_WAIT0()  asm volatile("cp.async.wait_group 0;" ::: "memory")

// ================= Kernel 0: gather + fp16 pre-convert (coalesced) =================
__global__ void __launch_bounds__(256) pre_cvt_h(
    const float* __restrict__ x,
    const float* __restrict__ Wq, const float* __restrict__ Wk, const float* __restrict__ Wv)
{
    const int blk  = blockIdx.x;
    const int rloc = threadIdx.x >> 5;
    const int lane = threadIdx.x & 31;

    const float* src;
    __half* dst;
    if (blk < 12544) {
        int p  = blk * 8 + rloc;
        int b  = p / 3136;
        int r  = p - b * 3136;
        int w  = r / 49;
        int t  = r - w * 49;
        int wy = w >> 3, wx = w & 7;
        int ty = t / 7,  tx = t - ty * 7;
        src = x + (size_t)((b * 56 + wy * 7 + ty) * 56 + wx * 7 + tx) * CDIM + lane * 8;
        dst = g_xh + (size_t)p * CDIM + lane * 8;
    } else {
        int r  = (blk - 12544) * 8 + rloc;
        int pr = r >> 8, wr = r & 255;
        const float* W = (pr == 0) ? Wq : ((pr == 1) ? Wk : Wv);
        src = W + (size_t)wr * CDIM + lane * 8;
        dst = g_wh + (size_t)r * CDIM + lane * 8;
    }
    float4 v0 = *(const float4*)(src);
    float4 v1 = *(const float4*)(src + 4);
    __half2 o[4];
    o[0] = __float22half2_rn(make_float2(v0.x, v0.y));
    o[1] = __float22half2_rn(make_float2(v0.z, v0.w));
    o[2] = __float22half2_rn(make_float2(v1.x, v1.y));
    o[3] = __float22half2_rn(make_float2(v1.z, v1.w));
    *(uint4*)dst = *(uint4*)o;
}

// ================= Kernel 1: QKV projection (fp16 HMMA, 4-stage pipeline) =================
#define HST 40
#define STAGE_HALVES (2 * 128 * HST)
#define NSTAGE 4
#define PROJ_SMEM_BYTES (NSTAGE * STAGE_HALVES * 2)   // 81920

__global__ void __launch_bounds__(128) qkv_proj_fp16(
    const float* __restrict__ bq, const float* __restrict__ bk, const float* __restrict__ bv)
{
    extern __shared__ __align__(16) __half hsm[];

    const int tid  = threadIdx.x;
    const int warp = tid >> 5;
    const int lane = tid & 31;
    const int g    = lane >> 2;
    const int tig  = lane & 3;
    const int wm   = warp >> 1;
    const int wn   = warp & 1;

    const int p_block = blockIdx.y * 128;
    const int nb      = blockIdx.x;
    const int proj    = nb >> 1;
    const int dloc    = (nb & 1) * 128;
    const float* __restrict__ bias = (proj == 0) ? bq : ((proj == 1) ? bk : bv);

    const int lrow = tid >> 2;
    const int seg  = tid & 3;
    const __half* Ag = g_xh + (size_t)(p_block + lrow) * CDIM + seg * 8;
    const __half* Bg = g_wh + (size_t)(nb * 128 + lrow) * CDIM + seg * 8;
    const uint32_t sbase = smem_u32(hsm);

    auto issue_stage = [&](int stage, int chunk) {
        const uint32_t sA = sbase + (uint32_t)(stage * STAGE_HALVES) * 2;
        const uint32_t sB = sA + 128 * HST * 2;
        const int ko = chunk * 32;
        #pragma unroll
        for (int i = 0; i < 4; i++) {
            const uint32_t ro = (uint32_t)((lrow + 32 * i) * HST + seg * 8) * 2;
            CP_ASYNC16(sA + ro, Ag + (size_t)(32 * i) * CDIM + ko);
            CP_ASYNC16(sB + ro, Bg + (size_t)(32 * i) * CDIM + ko);
        }
        CP_COMMIT();
    };

    issue_stage(0, 0);
    issue_stage(1, 1);
    issue_stage(2, 2);

    float acc[4][8][4] = {};

    for (int kt = 0; kt < 8; kt++) {
        if (kt <= 5)      { CP_WAIT2(); }
        else if (kt == 6) { CP_WAIT1(); }
        else              { CP_WAIT0(); }
        __syncthreads();

        if (kt + 3 < 8)
            issue_stage((kt + 3) & 3, kt + 3);

        const uint32_t* As32 = (const uint32_t*)(hsm + (kt & 3) * STAGE_HALVES);
        const uint32_t* Bs32 = As32 + 128 * (HST / 2);

        #pragma unroll
        for (int ks = 0; ks < 2; ks++) {
            const int ko = ks * 8;
            unsigned a[4][4];
            unsigned b[8][2];
            #pragma unroll
            for (int mt = 0; mt < 4; mt++) {
                int row = wm * 64 + mt * 16 + g;
                a[mt][0] = As32[row * 20 + ko + tig];
                a[mt][1] = As32[(row + 8) * 20 + ko + tig];
                a[mt][2] = As32[row * 20 + ko + 4 + tig];
                a[mt][3] = As32[(row + 8) * 20 + ko + 4 + tig];
            }
            #pragma unroll
            for (int nt = 0; nt < 8; nt++) {
                int nrow = wn * 64 + nt * 8 + g;
                b[nt][0] = Bs32[nrow * 20 + ko + tig];
                b[nt][1] = Bs32[nrow * 20 + ko + 4 + tig];
            }
            #pragma unroll
            for (int mt = 0; mt < 4; mt++)
                #pragma unroll
                for (int nt = 0; nt < 8; nt++)
                    mma_f16(acc[mt][nt], a[mt], b[nt]);
        }
    }

    // ---- epilogue: bias add + fp16 store ----
    const size_t proj_off = (size_t)proj * M_TOK * CDIM;
    float bvs[8][2];
    #pragma unroll
    for (int nt = 0; nt < 8; nt++) {
        int d = dloc + wn * 64 + nt * 8 + tig * 2;
        bvs[nt][0] = bias[d];
        bvs[nt][1] = bias[d + 1];
    }
    #pragma unroll
    for (int mt = 0; mt < 4; mt++) {
        int p0 = p_block + wm * 64 + mt * 16 + g;
        __half* r0 = g_qkvh + proj_off + (size_t)p0 * CDIM;
        __half* r1 = r0 + 8 * CDIM;
        #pragma unroll
        for (int nt = 0; nt < 8; nt++) {
            int d = dloc + wn * 64 + nt * 8 + tig * 2;
            *(unsigned*)(r0 + d) = pack_h2(acc[mt][nt][0] + bvs[nt][0], acc[mt][nt][1] + bvs[nt][1]);
            *(unsigned*)(r1 + d) = pack_h2(acc[mt][nt][2] + bvs[nt][0], acc[mt][nt][3] + bvs[nt][1]);
        }
    }
}

// ================= Kernel 2: fp16 tensor-core attention (round-14, unchanged) =================
#define QH_ST 40
#define VT_ST 72

__global__ void __launch_bounds__(128, 8) attn_kernel(float* __restrict__ out)
{
    __shared__ __align__(16) __half qs[64 * QH_ST];
    __shared__ __align__(16) __half ks[56 * QH_ST];
    __shared__ __align__(16) __half vt[32 * VT_ST];

    const int w   = blockIdx.x;
    const int h   = blockIdx.y;
    const int tid = threadIdx.x;

    const size_t base = (size_t)w * TWIN * CDIM + (size_t)h * HD;
    const uint32_t qs_b = smem_u32(qs);
    const uint32_t ks_b = smem_u32(ks);

    // ---- cp.async q,k issued FIRST ----
    for (int idx = tid; idx < 2 * TWIN * 4; idx += 128) {
        int mat = (idx >= TWIN * 4) ? 1 : 0;
        int rem = idx - mat * (TWIN * 4);
        int t   = rem >> 2;
        int seg = rem & 3;
        uint32_t dst = (mat ? ks_b : qs_b) + (uint32_t)(t * QH_ST + seg * 8) * 2;
        CP_ASYNC16(dst, g_qkvh + (size_t)mat * M_TOK * CDIM + base + (size_t)t * CDIM + seg * 8);
    }
    CP_COMMIT();

    // ---- zero pads (overlap with cp.async) ----
    for (int i = tid; i < 15 * QH_ST; i += 128) qs[49 * QH_ST + i] = __half(0.f);
    for (int i = tid; i < 7 * QH_ST; i += 128)  ks[49 * QH_ST + i] = __half(0.f);
    for (int i = tid; i < 32 * 16; i += 128) {
        int d = i >> 4, c = 49 + (i & 15);
        vt[d * VT_ST + c] = __half(0.f);
    }

    // ---- v transposed (LDG+STS, overlaps cp.async in flight) ----
    for (int idx = tid; idx < TWIN * 4; idx += 128) {
        int t   = idx >> 2;
        int seg = idx & 3;
        uint4 raw = *(const uint4*)(g_qkvh + (size_t)2 * M_TOK * CDIM + base + (size_t)t * CDIM + seg * 8);
        __half hv[8];
        *(uint4*)hv = raw;
        #pragma unroll
        for (int i = 0; i < 8; i++)
            vt[(seg * 8 + i) * VT_ST + t] = hv[i];
    }
    CP_WAIT0();
    __syncthreads();

    const int warp = tid >> 5;
    const int lane = tid & 31;
    const int g    = lane >> 2;
    const int tig  = lane & 3;
    const int i0   = warp * 16;

    const uint32_t* qw = (const uint32_t*)qs;
    const uint32_t* kw = (const uint32_t*)ks;
    const uint32_t* vw = (const uint32_t*)vt;

    float acc[7][4] = {};
    #pragma unroll
    for (int ks16 = 0; ks16 < 2; ks16++) {
        const int c0 = ks16 * 8;
        unsigned a[4];
        a[0] = qw[(i0 + g) * 20 + c0 + tig];
        a[1] = qw[(i0 + g + 8) * 20 + c0 + tig];
        a[2] = qw[(i0 + g) * 20 + c0 + 4 + tig];
        a[3] = qw[(i0 + g + 8) * 20 + c0 + 4 + tig];
        #pragma unroll
        for (int nt = 0; nt < 7; nt++) {
            unsigned b[2];
            b[0] = kw[(nt * 8 + g) * 20 + c0 + tig];
            b[1] = kw[(nt * 8 + g) * 20 + c0 + 4 + tig];
            mma_f16(acc[nt], a, b);
        }
    }

    #pragma unroll
    for (int nt = 0; nt < 7; nt++) {
        acc[nt][0] *= 0.0625f; acc[nt][1] *= 0.0625f;
        acc[nt][2] *= 0.0625f; acc[nt][3] *= 0.0625f;
    }
    acc[6][1] = -1e30f; acc[6][3] = -1e30f;
    if (tig > 0) { acc[6][0] = -1e30f; acc[6][2] = -1e30f; }

    float m0 = -1e30f, m1 = -1e30f;
    #pragma unroll
    for (int nt = 0; nt < 7; nt++) {
        m0 = fmaxf(m0, fmaxf(acc[nt][0], acc[nt][1]));
        m1 = fmaxf(m1, fmaxf(acc[nt][2], acc[nt][3]));
    }
    m0 = fmaxf(m0, __shfl_xor_sync(0xffffffffu, m0, 1));
    m0 = fmaxf(m0, __shfl_xor_sync(0xffffffffu, m0, 2));
    m1 = fmaxf(m1, __shfl_xor_sync(0xffffffffu, m1, 1));
    m1 = fmaxf(m1, __shfl_xor_sync(0xffffffffu, m1, 2));

    float s0 = 0.f, s1 = 0.f;
    #pragma unroll
    for (int nt = 0; nt < 7; nt++) {
        acc[nt][0] = __expf(acc[nt][0] - m0);
        acc[nt][1] = __expf(acc[nt][1] - m0);
        acc[nt][2] = __expf(acc[nt][2] - m1);
        acc[nt][3] = __expf(acc[nt][3] - m1);
        s0 += acc[nt][0] + acc[nt][1];
        s1 += acc[nt][2] + acc[nt][3];
    }
    s0 += __shfl_xor_sync(0xffffffffu, s0, 1);
    s0 += __shfl_xor_sync(0xffffffffu, s0, 2);
    s1 += __shfl_xor_sync(0xffffffffu, s1, 1);
    s1 += __shfl_xor_sync(0xffffffffu, s1, 2);
    const float inv0 = 1.f / s0, inv1 = 1.f / s1;
    #pragma unroll
    for (int nt = 0; nt < 7; nt++) {
        acc[nt][0] *= inv0; acc[nt][1] *= inv0;
        acc[nt][2] *= inv1; acc[nt][3] *= inv1;
    }

    float oacc[4][4] = {};
    #pragma unroll
    for (int t = 0; t < 4; t++) {
        const int n0 = 2 * t, n1 = 2 * t + 1;
        unsigned pa[4];
        pa[0] = pack_h2(acc[n0][0], acc[n0][1]);
        pa[1] = pack_h2(acc[n0][2], acc[n0][3]);
        pa[2] = (n1 < 7) ? pack_h2(acc[n1][0], acc[n1][1]) : 0u;
        pa[3] = (n1 < 7) ? pack_h2(acc[n1][2], acc[n1][3]) : 0u;
        #pragma unroll
        for (int dt = 0; dt < 4; dt++) {
            unsigned b[2];
            b[0] = vw[(dt * 8 + g) * 36 + 8 * t + tig];
            b[1] = vw[(dt * 8 + g) * 36 + 8 * t + tig + 4];
            mma_f16(oacc[dt], pa, b);
        }
    }

    const int row0 = i0 + g;
    const int row1 = i0 + 8 + g;
    if (row0 < TWIN) {
        float* o = out + ((size_t)w * TWIN + row0) * CDIM + (size_t)h * HD;
        #pragma unroll
        for (int dt = 0; dt < 4; dt++)
            *(float2*)&o[dt * 8 + tig * 2] = make_float2(oacc[dt][0], oacc[dt][1]);
    }
    if (row1 < TWIN) {
        float* o = out + ((size_t)w * TWIN + row1) * CDIM + (size_t)h * HD;
        #pragma unroll
        for (int dt = 0; dt < 4; dt++)
            *(float2*)&o[dt * 8 + tig * 2] = make_float2(oacc[dt][2], oacc[dt][3]);
    }
}

// ================= launch =================
extern "C" void kernel_launch(void* const* d_in, const int* in_sizes, int n_in,
                              void* d_out, int out_size) {
    const float* x  = (const float*)d_in[0];
    const float* Wq = (const float*)d_in[1];
    const float* bq = (const float*)d_in[2];
    const float* Wk = (const float*)d_in[3];
    const float* bk = (const float*)d_in[4];
    const float* Wv = (const float*)d_in[5];
    const float* bv = (const float*)d_in[6];
    float* out = (float*)d_out;

    cudaFuncSetAttribute(qkv_proj_fp16,
                         cudaFuncAttributeMaxDynamicSharedMemorySize, PROJ_SMEM_BYTES);

    pre_cvt_h<<<12640, 256>>>(x, Wq, Wk, Wv);

    dim3 g1(6, M_TOK / 128);
    qkv_proj_fp16<<<g1, 128, PROJ_SMEM_BYTES>>>(bq, bk, bv);

    dim3 g2(NWIN, NHEADS);
    attn_kernel<<<g2, 128>>>(out);
}